// round 7
// baseline (speedup 1.0000x reference)
#include <cuda_runtime.h>
#include <cuda_fp16.h>
#include <cstdint>

#define E_EDGES 50000
#define EPAD    50048          // 391 * 128
#define KFLAT   8192           // 128 (c) * 64 (i)
#define MTILES  391
#define BK      64             // fp16 K-elements per stage (128B rows)
#define NT      (KFLAT / BK)   // 128 k-tiles

// fp16 hi/lo split scratch: A (per-edge bilinear input) and W^T
__device__ __half g_Ahi[(size_t)EPAD * KFLAT];
__device__ __half g_Alo[(size_t)EPAD * KFLAT];
__device__ __half g_Whi[(size_t)128 * KFLAT];   // [o][k], k = c*64+i
__device__ __half g_Wlo[(size_t)128 * KFLAT];

// ---------------- helpers ----------------
__device__ __forceinline__ uint32_t smem_u32(const void* p) {
    uint32_t a;
    asm("{ .reg .u64 t; cvta.to.shared.u64 t, %1; cvt.u32.u64 %0, t; }" : "=r"(a) : "l"(p));
    return a;
}
#define SWZ128(x) ((x) ^ (((x) >> 3) & 0x70))

__device__ __forceinline__ void cp16(uint32_t dst, const void* src) {
    asm volatile("cp.async.cg.shared.global [%0], [%1], 16;" :: "r"(dst), "l"(src));
}
#define CP_COMMIT() asm volatile("cp.async.commit_group;" ::: "memory")
#define CP_WAIT(n)  asm volatile("cp.async.wait_group %0;" :: "n"(n) : "memory")

__device__ __forceinline__ void ldmx4(uint32_t* d, uint32_t addr) {
    asm volatile("ldmatrix.sync.aligned.m8n8.x4.shared.b16 {%0,%1,%2,%3}, [%4];"
        : "=r"(d[0]), "=r"(d[1]), "=r"(d[2]), "=r"(d[3]) : "r"(addr));
}
__device__ __forceinline__ void mma16816(float* c, const uint32_t* a, const uint32_t* b) {
    asm volatile(
        "mma.sync.aligned.m16n8k16.row.col.f32.f16.f16.f32 "
        "{%0,%1,%2,%3}, {%4,%5,%6,%7}, {%8,%9}, {%0,%1,%2,%3};"
        : "+f"(c[0]), "+f"(c[1]), "+f"(c[2]), "+f"(c[3])
        : "r"(a[0]), "r"(a[1]), "r"(a[2]), "r"(a[3]), "r"(b[0]), "r"(b[1]));
}
__device__ __forceinline__ unsigned pack_hh(__half a, __half b) {
    __half2 t = __halves2half2(a, b);
    return *reinterpret_cast<unsigned*>(&t);
}
__device__ __forceinline__ unsigned pack_ff(float a, float b) {
    __half2 t = __floats2half2_rn(a, b);
    return *reinterpret_cast<unsigned*>(&t);
}

// ---------------------------------------------------------------------------
// Kernel 0: W split + transpose.  g_Whi/lo[o][c*64+i] = split(W[c,i,o]).
// ---------------------------------------------------------------------------
__global__ void __launch_bounds__(256) wsplit_kernel(const float* __restrict__ W) {
    const int c = blockIdx.x;
    const int tid = threadIdx.x;
    __shared__ __align__(16) float sW[64 * 128];   // [i][o]
    #pragma unroll
    for (int l = 0; l < 8; l++)
        ((float4*)sW)[tid + 256 * l] = ((const float4*)(W + (size_t)c * 8192))[tid + 256 * l];
    __syncthreads();

    const int o  = tid >> 1;
    const int i0 = (tid & 1) * 32;
    size_t base = (size_t)o * KFLAT + c * 64 + i0;
    #pragma unroll
    for (int g = 0; g < 4; g++) {
        __half h[8]; float r[8];
        #pragma unroll
        for (int j = 0; j < 8; j++) {
            float a = sW[(i0 + g * 8 + j) * 128 + o];
            h[j] = __float2half_rn(a);
            r[j] = a - __half2float(h[j]);
        }
        uint4 vh = make_uint4(pack_hh(h[0],h[1]), pack_hh(h[2],h[3]), pack_hh(h[4],h[5]), pack_hh(h[6],h[7]));
        uint4 vl = make_uint4(pack_ff(r[0],r[1]), pack_ff(r[2],r[3]), pack_ff(r[4],r[5]), pack_ff(r[6],r[7]));
        *(uint4*)&g_Whi[base + g * 8] = vh;
        *(uint4*)&g_Wlo[base + g * 8] = vl;
    }
}

// ---------------------------------------------------------------------------
// Kernel 1: per-edge prep with fp16 hi/lo split output.
// A[e,i,c] = sum_kk P[e,i,kk] * m[e*8+kk, c],  P = rbf @ sph[:, :8].
// Stores A k-flattened:  As[e][c*64 + i].
// ---------------------------------------------------------------------------
__global__ void __launch_bounds__(256) prep_kernel(
    const float* __restrict__ rbf,   // (E, 64, 16)
    const float* __restrict__ sph,   // (E, 16, 16)
    const float* __restrict__ m)     // (E*8, 128)
{
    const int e   = blockIdx.x;
    const int tid = threadIdx.x;

    if (e >= E_EDGES) {
        size_t base = (size_t)e * KFLAT;
        uint4 z = make_uint4(0, 0, 0, 0);
        #pragma unroll
        for (int l = 0; l < 4; l++) {
            ((uint4*)(g_Ahi + base))[tid + 256 * l] = z;
            ((uint4*)(g_Alo + base))[tid + 256 * l] = z;
        }
        return;
    }

    __shared__ __align__(16) float s_rbf[1024];   // [i][s]
    __shared__ __align__(16) float s_sph[128];    // [s][kk]
    __shared__ __align__(16) float s_m[1024];     // [kk][c]
    __shared__ __align__(16) float s_P[512];      // [i][kk]

    ((float4*)s_rbf)[tid] = ((const float4*)(rbf + (size_t)e * 1024))[tid];
    ((float4*)s_m)[tid]   = ((const float4*)(m   + (size_t)e * 1024))[tid];
    if (tid < 128) {
        int s = tid >> 3, kk = tid & 7;
        s_sph[tid] = sph[(size_t)e * 256 + s * 16 + kk];
    }
    __syncthreads();

    #pragma unroll
    for (int rq = 0; rq < 2; rq++) {
        int o = tid + 256 * rq;
        int i = o >> 3, kk = o & 7;
        float acc = 0.f;
        #pragma unroll
        for (int s = 0; s < 16; s++)
            acc += s_rbf[i * 16 + s] * s_sph[s * 8 + kk];
        s_P[o] = acc;
    }
    __syncthreads();

    // thread owns one channel c, 32 contiguous i -> 64B coalesced stores
    const int c  = tid >> 1;
    const int i0 = (tid & 1) * 32;
    float mc[8];
    #pragma unroll
    for (int kk = 0; kk < 8; kk++) mc[kk] = s_m[kk * 128 + c];

    size_t base = (size_t)e * KFLAT + c * 64 + i0;
    #pragma unroll
    for (int g = 0; g < 4; g++) {
        __half h[8]; float r[8];
        #pragma unroll
        for (int j = 0; j < 8; j++) {
            int i = i0 + g * 8 + j;
            float acc = 0.f;
            #pragma unroll
            for (int kk = 0; kk < 8; kk++)
                acc += s_P[i * 8 + kk] * mc[kk];
            h[j] = __float2half_rn(acc);
            r[j] = acc - __half2float(h[j]);
        }
        uint4 vh = make_uint4(pack_hh(h[0],h[1]), pack_hh(h[2],h[3]), pack_hh(h[4],h[5]), pack_hh(h[6],h[7]));
        uint4 vl = make_uint4(pack_ff(r[0],r[1]), pack_ff(r[2],r[3]), pack_ff(r[4],r[5]), pack_ff(r[6],r[7]));
        *(uint4*)&g_Ahi[base + g * 8] = vh;
        *(uint4*)&g_Alo[base + g * 8] = vl;
    }
}

// ---------------------------------------------------------------------------
// Kernel 2: HMMA GEMM, 512 threads / 16 warps (4 per SMSP) for latency hiding.
// out[E,128] = (Ahi+Alo)[E,8192] @ (Whi+Wlo)^T, 3 error-compensated passes.
// CTA tile 128x128, BK=64, double-buffered cp.async; warp tile 32x32.
// ---------------------------------------------------------------------------
#define OFF_AHI 0
#define OFF_ALO 16384
#define OFF_BHI 32768
#define OFF_BLO 49152
#define STAGE_BYTES 65536
#define SMEM_TOTAL_GEMM (2 * STAGE_BYTES)

__global__ void __launch_bounds__(512, 1) gemm_kernel(float* __restrict__ out) {
    extern __shared__ char smem[];
    const uint32_t sbase = smem_u32(smem);
    const int tid  = threadIdx.x;
    const int wid  = tid >> 5, lane = tid & 31;
    const int warp_m = wid >> 2;        // 0..3 -> 32-row slab
    const int warp_n = wid & 3;         // 0..3 -> 32-col slab
    const int m_base = blockIdx.x * 128;

    // ---- staging mapping: thread -> (matrix, row), copies one full 128B row ----
    const int mat = tid >> 7;           // 0:Ahi 1:Alo 2:Bhi 3:Blo
    const int r   = tid & 127;
    const char* gsrc;
    uint32_t soff;
    switch (mat) {
        case 0:  gsrc = (const char*)g_Ahi + (size_t)(m_base + r) * (KFLAT * 2); soff = OFF_AHI; break;
        case 1:  gsrc = (const char*)g_Alo + (size_t)(m_base + r) * (KFLAT * 2); soff = OFF_ALO; break;
        case 2:  gsrc = (const char*)g_Whi + (size_t)r * (KFLAT * 2);            soff = OFF_BHI; break;
        default: gsrc = (const char*)g_Wlo + (size_t)r * (KFLAT * 2);            soff = OFF_BLO; break;
    }
    uint32_t swz[8];
    #pragma unroll
    for (int q = 0; q < 8; q++) swz[q] = soff + SWZ128(r * 128 + q * 16);

    auto load_stage = [&](int t, int buf) {
        const uint32_t su = sbase + buf * STAGE_BYTES;
        const size_t koff = (size_t)t * 128;
        #pragma unroll
        for (int q = 0; q < 8; q++)
            cp16(su + swz[q], gsrc + koff + q * 16);
    };

    // ---- ldmatrix per-thread byte offsets (unswizzled; swizzle at use) ----
    uint32_t aoff[2];
    #pragma unroll
    for (int mt = 0; mt < 2; mt++)
        aoff[mt] = (warp_m * 32 + mt * 16 + (lane & 15)) * 128 + (lane >> 4) * 16;
    uint32_t boff[2];
    #pragma unroll
    for (int p = 0; p < 2; p++) {
        int g = lane >> 3;
        int n = warp_n * 32 + (2 * p + (g >> 1)) * 8 + (lane & 7);
        boff[p] = n * 128 + (g & 1) * 16;
    }

    float acc[2][4][4];
    #pragma unroll
    for (int mt = 0; mt < 2; mt++)
        #pragma unroll
        for (int nt = 0; nt < 4; nt++)
            #pragma unroll
            for (int q = 0; q < 4; q++) acc[mt][nt][q] = 0.f;

    load_stage(0, 0);
    CP_COMMIT();

    #pragma unroll 1
    for (int t = 0; t < NT; t++) {
        const int buf = t & 1;
        if (t + 1 < NT) {
            load_stage(t + 1, (t + 1) & 1);
            CP_COMMIT();
            CP_WAIT(1);
        } else {
            CP_WAIT(0);
        }
        __syncthreads();

        const uint32_t su = sbase + buf * STAGE_BYTES;
        #pragma unroll
        for (int ks = 0; ks < 4; ks++) {
            const int kb = ks * 32;
            uint32_t ah[2][4], al[2][4], bh[4][2], bl[4][2];
            #pragma unroll
            for (int mt = 0; mt < 2; mt++) {
                ldmx4(ah[mt], su + OFF_AHI + SWZ128(aoff[mt] + kb));
                ldmx4(al[mt], su + OFF_ALO + SWZ128(aoff[mt] + kb));
            }
            #pragma unroll
            for (int p = 0; p < 2; p++) {
                uint32_t b4[4];
                ldmx4(b4, su + OFF_BHI + SWZ128(boff[p] + kb));
                bh[2*p][0] = b4[0]; bh[2*p][1] = b4[1];
                bh[2*p+1][0] = b4[2]; bh[2*p+1][1] = b4[3];
                ldmx4(b4, su + OFF_BLO + SWZ128(boff[p] + kb));
                bl[2*p][0] = b4[0]; bl[2*p][1] = b4[1];
                bl[2*p+1][0] = b4[2]; bl[2*p+1][1] = b4[3];
            }
            #pragma unroll
            for (int mt = 0; mt < 2; mt++)
                #pragma unroll
                for (int nt = 0; nt < 4; nt++) {
                    mma16816(acc[mt][nt], ah[mt], bh[nt]);
                    mma16816(acc[mt][nt], ah[mt], bl[nt]);
                    mma16816(acc[mt][nt], al[mt], bh[nt]);
                }
        }
        __syncthreads();
    }

    // ---- epilogue ----
    #pragma unroll
    for (int mt = 0; mt < 2; mt++) {
        const int row0 = m_base + warp_m * 32 + mt * 16 + (lane >> 2);
        #pragma unroll
        for (int nt = 0; nt < 4; nt++) {
            const int col = warp_n * 32 + nt * 8 + (lane & 3) * 2;
            if (row0 < E_EDGES)
                *(float2*)&out[(size_t)row0 * 128 + col] =
                    make_float2(acc[mt][nt][0], acc[mt][nt][1]);
            if (row0 + 8 < E_EDGES)
                *(float2*)&out[(size_t)(row0 + 8) * 128 + col] =
                    make_float2(acc[mt][nt][2], acc[mt][nt][3]);
        }
    }
}

// ---------------------------------------------------------------------------
extern "C" void kernel_launch(void* const* d_in, const int* in_sizes, int n_in,
                              void* d_out, int out_size) {
    const float* rbf = (const float*)d_in[0];   // (E, 64, 16)
    const float* sph = (const float*)d_in[1];   // (E, 16, 16)
    const float* m   = (const float*)d_in[2];   // (E*8, 128)
    const float* w   = (const float*)d_in[3];   // (128, 64, 128)
    float* out = (float*)d_out;

    cudaFuncSetAttribute(gemm_kernel, cudaFuncAttributeMaxDynamicSharedMemorySize, SMEM_TOTAL_GEMM);

    wsplit_kernel<<<128, 256>>>(w);
    prep_kernel<<<EPAD, 256>>>(rbf, sph, m);
    gemm_kernel<<<MTILES, 512, SMEM_TOTAL_GEMM>>>(out);
}

// round 8
// speedup vs baseline: 1.9511x; 1.9511x over previous
#include <cuda_runtime.h>
#include <cuda_fp16.h>
#include <cstdint>

#define E_EDGES 50000
#define EPAD    50048          // 391 * 128
#define KFLAT   8192           // 128 (c) * 64 (i)
#define MTILES  391
#define BK      64             // fp16 K-elements per stage (128B rows)
#define NT      (KFLAT / BK)   // 128 k-tiles

// fp16 scratch: A (per-edge bilinear input) and W^T
__device__ __half g_A[(size_t)EPAD * KFLAT];
__device__ __half g_W[(size_t)128 * KFLAT];   // [o][k], k = c*64+i

// ---------------- helpers ----------------
__device__ __forceinline__ uint32_t smem_u32(const void* p) {
    uint32_t a;
    asm("{ .reg .u64 t; cvta.to.shared.u64 t, %1; cvt.u32.u64 %0, t; }" : "=r"(a) : "l"(p));
    return a;
}
#define SWZ128(x) ((x) ^ (((x) >> 3) & 0x70))

__device__ __forceinline__ void cp16(uint32_t dst, const void* src) {
    asm volatile("cp.async.cg.shared.global [%0], [%1], 16;" :: "r"(dst), "l"(src));
}
#define CP_COMMIT() asm volatile("cp.async.commit_group;" ::: "memory")
#define CP_WAIT(n)  asm volatile("cp.async.wait_group %0;" :: "n"(n) : "memory")

__device__ __forceinline__ void ldmx4(uint32_t* d, uint32_t addr) {
    asm volatile("ldmatrix.sync.aligned.m8n8.x4.shared.b16 {%0,%1,%2,%3}, [%4];"
        : "=r"(d[0]), "=r"(d[1]), "=r"(d[2]), "=r"(d[3]) : "r"(addr));
}
__device__ __forceinline__ void mma16816(float* c, const uint32_t* a, const uint32_t* b) {
    asm volatile(
        "mma.sync.aligned.m16n8k16.row.col.f32.f16.f16.f32 "
        "{%0,%1,%2,%3}, {%4,%5,%6,%7}, {%8,%9}, {%0,%1,%2,%3};"
        : "+f"(c[0]), "+f"(c[1]), "+f"(c[2]), "+f"(c[3])
        : "r"(a[0]), "r"(a[1]), "r"(a[2]), "r"(a[3]), "r"(b[0]), "r"(b[1]));
}
__device__ __forceinline__ unsigned pack_ff(float a, float b) {
    __half2 t = __floats2half2_rn(a, b);
    return *reinterpret_cast<unsigned*>(&t);
}

// ---------------------------------------------------------------------------
// Kernel 0: W transpose to fp16.  g_W[o][c*64+i] = (half)W[c,i,o].
// ---------------------------------------------------------------------------
__global__ void __launch_bounds__(256) wsplit_kernel(const float* __restrict__ W) {
    const int c = blockIdx.x;
    const int tid = threadIdx.x;
    __shared__ __align__(16) float sW[64 * 128];   // [i][o]
    #pragma unroll
    for (int l = 0; l < 8; l++)
        ((float4*)sW)[tid + 256 * l] = ((const float4*)(W + (size_t)c * 8192))[tid + 256 * l];
    __syncthreads();

    const int o  = tid >> 1;
    const int i0 = (tid & 1) * 32;
    size_t base = (size_t)o * KFLAT + c * 64 + i0;
    #pragma unroll
    for (int g = 0; g < 4; g++) {
        float a[8];
        #pragma unroll
        for (int j = 0; j < 8; j++)
            a[j] = sW[(i0 + g * 8 + j) * 128 + o];
        uint4 vh = make_uint4(pack_ff(a[0],a[1]), pack_ff(a[2],a[3]),
                              pack_ff(a[4],a[5]), pack_ff(a[6],a[7]));
        *(uint4*)&g_W[base + g * 8] = vh;
    }
}

// ---------------------------------------------------------------------------
// Kernel 1: per-edge prep, fp16 output.
// A[e,i,c] = sum_kk P[e,i,kk] * m[e*8+kk, c],  P = rbf @ sph[:, :8].
// Stores A k-flattened:  g_A[e][c*64 + i].
// ---------------------------------------------------------------------------
__global__ void __launch_bounds__(256) prep_kernel(
    const float* __restrict__ rbf,   // (E, 64, 16)
    const float* __restrict__ sph,   // (E, 16, 16)
    const float* __restrict__ m)     // (E*8, 128)
{
    const int e   = blockIdx.x;
    const int tid = threadIdx.x;

    if (e >= E_EDGES) {
        size_t base = (size_t)e * KFLAT;
        uint4 z = make_uint4(0, 0, 0, 0);
        #pragma unroll
        for (int l = 0; l < 2; l++)
            ((uint4*)(g_A + base))[tid + 256 * l] = z;
        return;
    }

    __shared__ __align__(16) float s_rbf[1024];   // [i][s]
    __shared__ __align__(16) float s_sph[128];    // [s][kk]
    __shared__ __align__(16) float s_m[1024];     // [kk][c]
    __shared__ __align__(16) float s_P[512];      // [i][kk]

    ((float4*)s_rbf)[tid] = ((const float4*)(rbf + (size_t)e * 1024))[tid];
    ((float4*)s_m)[tid]   = ((const float4*)(m   + (size_t)e * 1024))[tid];
    if (tid < 128) {
        int s = tid >> 3, kk = tid & 7;
        s_sph[tid] = sph[(size_t)e * 256 + s * 16 + kk];
    }
    __syncthreads();

    #pragma unroll
    for (int rq = 0; rq < 2; rq++) {
        int o = tid + 256 * rq;
        int i = o >> 3, kk = o & 7;
        float acc = 0.f;
        #pragma unroll
        for (int s = 0; s < 16; s++)
            acc += s_rbf[i * 16 + s] * s_sph[s * 8 + kk];
        s_P[o] = acc;
    }
    __syncthreads();

    // thread owns one channel c, 32 contiguous i -> 64B coalesced stores
    const int c  = tid >> 1;
    const int i0 = (tid & 1) * 32;
    float mc[8];
    #pragma unroll
    for (int kk = 0; kk < 8; kk++) mc[kk] = s_m[kk * 128 + c];

    size_t base = (size_t)e * KFLAT + c * 64 + i0;
    #pragma unroll
    for (int g = 0; g < 4; g += 2) {
        float a[16];
        #pragma unroll
        for (int j = 0; j < 16; j++) {
            int i = i0 + g * 8 + j;
            float acc = 0.f;
            #pragma unroll
            for (int kk = 0; kk < 8; kk++)
                acc += s_P[i * 8 + kk] * mc[kk];
            a[j] = acc;
        }
        uint4 v0 = make_uint4(pack_ff(a[0],a[1]),  pack_ff(a[2],a[3]),
                              pack_ff(a[4],a[5]),  pack_ff(a[6],a[7]));
        uint4 v1 = make_uint4(pack_ff(a[8],a[9]),  pack_ff(a[10],a[11]),
                              pack_ff(a[12],a[13]), pack_ff(a[14],a[15]));
        *(uint4*)&g_A[base + g * 8]     = v0;
        *(uint4*)&g_A[base + g * 8 + 8] = v1;
    }
}

// ---------------------------------------------------------------------------
// Kernel 2: single-pass fp16 HMMA GEMM.  out[E,128] = A[E,8192] @ W^T.
// CTA tile 128x128, BK=64 double-buffered cp.async, 8 warps (2x4),
// warp tile 64x32, 2 CTAs/SM.
// ---------------------------------------------------------------------------
#define OFF_A 0
#define OFF_B 16384
#define STAGE_BYTES 32768
#define SMEM_TOTAL_GEMM (2 * STAGE_BYTES)

__global__ void __launch_bounds__(256, 2) gemm_kernel(float* __restrict__ out) {
    extern __shared__ char smem[];
    const uint32_t sbase = smem_u32(smem);
    const int tid  = threadIdx.x;
    const int wid  = tid >> 5, lane = tid & 31;
    const int warp_m = wid >> 2;        // 0..1 -> 64-row slab
    const int warp_n = wid & 3;         // 0..3 -> 32-col slab
    const int m_base = blockIdx.x * 128;

    // ---- staging: thread -> one 128B row (tid<128: A row, else W row) ----
    const int r = tid & 127;
    const char* gsrc = (tid < 128)
        ? (const char*)g_A + (size_t)(m_base + r) * (KFLAT * 2)
        : (const char*)g_W + (size_t)r * (KFLAT * 2);
    const uint32_t soff = (tid < 128) ? OFF_A : OFF_B;
    uint32_t swz[8];
    #pragma unroll
    for (int q = 0; q < 8; q++) swz[q] = soff + SWZ128(r * 128 + q * 16);

    auto load_stage = [&](int t, int buf) {
        const uint32_t su = sbase + buf * STAGE_BYTES;
        const size_t koff = (size_t)t * 128;
        #pragma unroll
        for (int q = 0; q < 8; q++)
            cp16(su + swz[q], gsrc + koff + q * 16);
    };

    // ---- ldmatrix per-thread byte offsets (unswizzled; swizzle at use) ----
    uint32_t aoff[4];
    #pragma unroll
    for (int mt = 0; mt < 4; mt++)
        aoff[mt] = (warp_m * 64 + mt * 16 + (lane & 15)) * 128 + (lane >> 4) * 16;
    uint32_t boff[2];
    #pragma unroll
    for (int p = 0; p < 2; p++) {
        int g = lane >> 3;
        int n = warp_n * 32 + (2 * p + (g >> 1)) * 8 + (lane & 7);
        boff[p] = n * 128 + (g & 1) * 16;
    }

    float acc[4][4][4];
    #pragma unroll
    for (int mt = 0; mt < 4; mt++)
        #pragma unroll
        for (int nt = 0; nt < 4; nt++)
            #pragma unroll
            for (int q = 0; q < 4; q++) acc[mt][nt][q] = 0.f;

    load_stage(0, 0);
    CP_COMMIT();

    #pragma unroll 1
    for (int t = 0; t < NT; t++) {
        const int buf = t & 1;
        if (t + 1 < NT) {
            load_stage(t + 1, (t + 1) & 1);
            CP_COMMIT();
            CP_WAIT(1);
        } else {
            CP_WAIT(0);
        }
        __syncthreads();

        const uint32_t su = sbase + buf * STAGE_BYTES;
        #pragma unroll
        for (int ks = 0; ks < 4; ks++) {
            const int kb = ks * 32;
            uint32_t ah[4][4], bh[4][2];
            #pragma unroll
            for (int mt = 0; mt < 4; mt++)
                ldmx4(ah[mt], su + OFF_A + SWZ128(aoff[mt] + kb));
            #pragma unroll
            for (int p = 0; p < 2; p++) {
                uint32_t b4[4];
                ldmx4(b4, su + OFF_B + SWZ128(boff[p] + kb));
                bh[2*p][0] = b4[0]; bh[2*p][1] = b4[1];
                bh[2*p+1][0] = b4[2]; bh[2*p+1][1] = b4[3];
            }
            #pragma unroll
            for (int mt = 0; mt < 4; mt++)
                #pragma unroll
                for (int nt = 0; nt < 4; nt++)
                    mma16816(acc[mt][nt], ah[mt], bh[nt]);
        }
        __syncthreads();
    }

    // ---- epilogue ----
    #pragma unroll
    for (int mt = 0; mt < 4; mt++) {
        const int row0 = m_base + warp_m * 64 + mt * 16 + (lane >> 2);
        #pragma unroll
        for (int nt = 0; nt < 4; nt++) {
            const int col = warp_n * 32 + nt * 8 + (lane & 3) * 2;
            if (row0 < E_EDGES)
                *(float2*)&out[(size_t)row0 * 128 + col] =
                    make_float2(acc[mt][nt][0], acc[mt][nt][1]);
            if (row0 + 8 < E_EDGES)
                *(float2*)&out[(size_t)(row0 + 8) * 128 + col] =
                    make_float2(acc[mt][nt][2], acc[mt][nt][3]);
        }
    }
}

// ---------------------------------------------------------------------------
extern "C" void kernel_launch(void* const* d_in, const int* in_sizes, int n_in,
                              void* d_out, int out_size) {
    const float* rbf = (const float*)d_in[0];   // (E, 64, 16)
    const float* sph = (const float*)d_in[1];   // (E, 16, 16)
    const float* m   = (const float*)d_in[2];   // (E*8, 128)
    const float* w   = (const float*)d_in[3];   // (128, 64, 128)
    float* out = (float*)d_out;

    cudaFuncSetAttribute(gemm_kernel, cudaFuncAttributeMaxDynamicSharedMemorySize, SMEM_TOTAL_GEMM);

    wsplit_kernel<<<128, 256>>>(w);
    prep_kernel<<<EPAD, 256>>>(rbf, sph, m);
    gemm_kernel<<<MTILES, 256, SMEM_TOTAL_GEMM>>>(out);
}

// round 10
// speedup vs baseline: 2.1641x; 1.1092x over previous
#include <cuda_runtime.h>
#include <cuda_fp16.h>
#include <cstdint>

#define E_EDGES 50000
#define EPAD    50048          // 391 * 128
#define KFLAT   8192           // 128 (c) * 64 (i)
#define MTILES  391
#define BK      64             // fp16 K-elements per stage (128B rows)
#define NT      (KFLAT / BK)   // 128 k-tiles

// fp16 scratch: A (per-edge bilinear input) and W^T
__device__ __half g_A[(size_t)EPAD * KFLAT];
__device__ __half g_W[(size_t)128 * KFLAT];   // [o][k], k = c*64+i

// ---------------- helpers ----------------
__device__ __forceinline__ uint32_t smem_u32(const void* p) {
    uint32_t a;
    asm("{ .reg .u64 t; cvta.to.shared.u64 t, %1; cvt.u32.u64 %0, t; }" : "=r"(a) : "l"(p));
    return a;
}
#define SWZ128(x) ((x) ^ (((x) >> 3) & 0x70))

__device__ __forceinline__ void cp16(uint32_t dst, const void* src) {
    asm volatile("cp.async.cg.shared.global [%0], [%1], 16;" :: "r"(dst), "l"(src));
}
#define CP_COMMIT() asm volatile("cp.async.commit_group;" ::: "memory")
#define CP_WAIT(n)  asm volatile("cp.async.wait_group %0;" :: "n"(n) : "memory")

__device__ __forceinline__ void ldmx4(uint32_t* d, uint32_t addr) {
    asm volatile("ldmatrix.sync.aligned.m8n8.x4.shared.b16 {%0,%1,%2,%3}, [%4];"
        : "=r"(d[0]), "=r"(d[1]), "=r"(d[2]), "=r"(d[3]) : "r"(addr));
}
__device__ __forceinline__ void mma16816(float* c, const uint32_t* a, const uint32_t* b) {
    asm volatile(
        "mma.sync.aligned.m16n8k16.row.col.f32.f16.f16.f32 "
        "{%0,%1,%2,%3}, {%4,%5,%6,%7}, {%8,%9}, {%0,%1,%2,%3};"
        : "+f"(c[0]), "+f"(c[1]), "+f"(c[2]), "+f"(c[3])
        : "r"(a[0]), "r"(a[1]), "r"(a[2]), "r"(a[3]), "r"(b[0]), "r"(b[1]));
}
__device__ __forceinline__ unsigned pack_ff(float a, float b) {
    __half2 t = __floats2half2_rn(a, b);
    return *reinterpret_cast<unsigned*>(&t);
}

// ---------------------------------------------------------------------------
// Kernel 0: W transpose to fp16.  g_W[o][c*64+i] = (half)W[c,i,o].
// ---------------------------------------------------------------------------
__global__ void __launch_bounds__(256) wsplit_kernel(const float* __restrict__ W) {
    const int c = blockIdx.x;
    const int tid = threadIdx.x;
    __shared__ __align__(16) float sW[64 * 128];   // [i][o]
    #pragma unroll
    for (int l = 0; l < 8; l++)
        ((float4*)sW)[tid + 256 * l] = ((const float4*)(W + (size_t)c * 8192))[tid + 256 * l];
    __syncthreads();

    const int o  = tid >> 1;
    const int i0 = (tid & 1) * 32;
    size_t base = (size_t)o * KFLAT + c * 64 + i0;
    #pragma unroll
    for (int g = 0; g < 4; g++) {
        float a[8];
        #pragma unroll
        for (int j = 0; j < 8; j++)
            a[j] = sW[(i0 + g * 8 + j) * 128 + o];
        uint4 vh = make_uint4(pack_ff(a[0],a[1]), pack_ff(a[2],a[3]),
                              pack_ff(a[4],a[5]), pack_ff(a[6],a[7]));
        *(uint4*)&g_W[base + g * 8] = vh;
    }
}

// ---------------------------------------------------------------------------
// Kernel 1: prep v2 — 2 edges per CTA, thread owns (edge, channel c) and the
// full 64-element i-row -> 128B contiguous stores (full sector coverage).
// A[e,i,c] = sum_kk P[e,i,kk] * m[e*8+kk, c],  P = rbf @ sph[:, :8].
// Stores g_A[e][c*64 + i].
// Blocks < E_EDGES/2 are fully valid; blocks >= E_EDGES/2 are all padding.
// ---------------------------------------------------------------------------
__global__ void __launch_bounds__(256) prep_kernel(
    const float* __restrict__ rbf,   // (E, 64, 16)
    const float* __restrict__ sph,   // (E, 16, 16)
    const float* __restrict__ m)     // (E*8, 128)
{
    const int blk = blockIdx.x;
    const int tid = threadIdx.x;
    const int e_loc = tid >> 7;          // 0/1
    const int c     = tid & 127;
    const int e     = blk * 2 + e_loc;

    if (blk >= E_EDGES / 2) {
        // pad edges: zero 128B row
        uint4 z = make_uint4(0, 0, 0, 0);
        uint4* dst = (uint4*)&g_A[(size_t)e * KFLAT + c * 64];
        #pragma unroll
        for (int q = 0; q < 8; q++) dst[q] = z;
        return;
    }

    __shared__ __align__(16) float s_rbf[2048];   // [e][i][s]
    __shared__ __align__(16) float s_m[2048];     // [e][kk][c]
    __shared__ __align__(16) float s_sph[256];    // [e][s][kk]
    __shared__ __align__(16) float s_P[1024];     // [e][i][kk]

    // linear copies: rbf and m are contiguous 2048-float slabs per block
    ((float4*)s_rbf)[tid]       = ((const float4*)(rbf + (size_t)blk * 2048))[tid];
    ((float4*)s_rbf)[tid + 256] = ((const float4*)(rbf + (size_t)blk * 2048))[tid + 256];
    ((float4*)s_m)[tid]         = ((const float4*)(m   + (size_t)blk * 2048))[tid];
    ((float4*)s_m)[tid + 256]   = ((const float4*)(m   + (size_t)blk * 2048))[tid + 256];
    {
        int el = tid >> 7, rest = tid & 127;
        int s = rest >> 3, kk = rest & 7;
        s_sph[el * 128 + rest] = sph[(size_t)(blk * 2 + el) * 256 + s * 16 + kk];
    }
    __syncthreads();

    // P: 1024 values, 4 per thread
    #pragma unroll
    for (int rq = 0; rq < 4; rq++) {
        int o = tid + 256 * rq;
        int el = o >> 9, idx = o & 511;
        int i = idx >> 3, kk = idx & 7;
        float acc = 0.f;
        #pragma unroll
        for (int s = 0; s < 16; s++)
            acc += s_rbf[el * 1024 + i * 16 + s] * s_sph[el * 128 + s * 8 + kk];
        s_P[o] = acc;
    }
    __syncthreads();

    // A: thread covers full i-row for its (e, c)
    float mc[8];
    #pragma unroll
    for (int kk = 0; kk < 8; kk++) mc[kk] = s_m[e_loc * 1024 + kk * 128 + c];

    const float* Pe = s_P + e_loc * 512;
    uint4* dst = (uint4*)&g_A[(size_t)e * KFLAT + c * 64];
    #pragma unroll
    for (int g = 0; g < 4; g++) {
        float a[16];
        #pragma unroll
        for (int j = 0; j < 16; j++) {
            int i = g * 16 + j;
            float acc = 0.f;
            #pragma unroll
            for (int kk = 0; kk < 8; kk++)
                acc += Pe[i * 8 + kk] * mc[kk];
            a[j] = acc;
        }
        dst[g * 2]     = make_uint4(pack_ff(a[0],a[1]),  pack_ff(a[2],a[3]),
                                    pack_ff(a[4],a[5]),  pack_ff(a[6],a[7]));
        dst[g * 2 + 1] = make_uint4(pack_ff(a[8],a[9]),  pack_ff(a[10],a[11]),
                                    pack_ff(a[12],a[13]), pack_ff(a[14],a[15]));
    }
}

// ---------------------------------------------------------------------------
// Kernel 2: single-pass fp16 HMMA GEMM, 3-stage cp.async ring, ONE
// __syncthreads per k-tile.  out[E,128] = A[E,8192] @ W^T.
// CTA tile 128x128, BK=64, 8 warps (2x4), warp tile 64x32, 2 CTAs/SM.
// ---------------------------------------------------------------------------
#define OFF_A 0
#define OFF_B 16384
#define STAGE_BYTES 32768
#define NSTAGE 3
#define SMEM_TOTAL_GEMM (NSTAGE * STAGE_BYTES)

__global__ void __launch_bounds__(256, 2) gemm_kernel(float* __restrict__ out) {
    extern __shared__ char smem[];
    const uint32_t sbase = smem_u32(smem);
    const int tid  = threadIdx.x;
    const int wid  = tid >> 5, lane = tid & 31;
    const int warp_m = wid >> 2;        // 0..1 -> 64-row slab
    const int warp_n = wid & 3;         // 0..3 -> 32-col slab
    const int m_base = blockIdx.x * 128;

    // ---- staging: thread -> one 128B row (tid<128: A row, else W row) ----
    const int r = tid & 127;
    const char* gsrc = (tid < 128)
        ? (const char*)g_A + (size_t)(m_base + r) * (KFLAT * 2)
        : (const char*)g_W + (size_t)r * (KFLAT * 2);
    const uint32_t soff = (tid < 128) ? OFF_A : OFF_B;
    uint32_t swz[8];
    #pragma unroll
    for (int q = 0; q < 8; q++) swz[q] = soff + SWZ128(r * 128 + q * 16);

    auto load_stage = [&](int t, int st) {
        const uint32_t su = sbase + st * STAGE_BYTES;
        const size_t koff = (size_t)t * 128;
        #pragma unroll
        for (int q = 0; q < 8; q++)
            cp16(su + swz[q], gsrc + koff + q * 16);
    };

    // ---- ldmatrix per-thread byte offsets (unswizzled; swizzle at use) ----
    uint32_t aoff[4];
    #pragma unroll
    for (int mt = 0; mt < 4; mt++)
        aoff[mt] = (warp_m * 64 + mt * 16 + (lane & 15)) * 128 + (lane >> 4) * 16;
    uint32_t boff[2];
    #pragma unroll
    for (int p = 0; p < 2; p++) {
        int g = lane >> 3;
        int n = warp_n * 32 + (2 * p + (g >> 1)) * 8 + (lane & 7);
        boff[p] = n * 128 + (g & 1) * 16;
    }

    float acc[4][4][4];
    #pragma unroll
    for (int mt = 0; mt < 4; mt++)
        #pragma unroll
        for (int nt = 0; nt < 4; nt++)
            #pragma unroll
            for (int q = 0; q < 4; q++) acc[mt][nt][q] = 0.f;

    load_stage(0, 0); CP_COMMIT();
    load_stage(1, 1); CP_COMMIT();

    int st = 0;                    // stage of tile t
    #pragma unroll 1
    for (int t = 0; t < NT; t++) {
        if (t == NT - 1) { CP_WAIT(0); } else { CP_WAIT(1); }
        __syncthreads();
        // stage (t+2)%3 was drained during tile t-1; safe to refill now
        if (t + 2 < NT) {
            int st2 = st + 2; if (st2 >= NSTAGE) st2 -= NSTAGE;
            load_stage(t + 2, st2);
            CP_COMMIT();
        }

        const uint32_t su = sbase + st * STAGE_BYTES;
        #pragma unroll
        for (int ks = 0; ks < 4; ks++) {
            const int kb = ks * 32;
            uint32_t ah[4][4], bh[4][2];
            #pragma unroll
            for (int mt = 0; mt < 4; mt++)
                ldmx4(ah[mt], su + OFF_A + SWZ128(aoff[mt] + kb));
            #pragma unroll
            for (int p = 0; p < 2; p++) {
                uint32_t b4[4];
                ldmx4(b4, su + OFF_B + SWZ128(boff[p] + kb));
                bh[2*p][0] = b4[0]; bh[2*p][1] = b4[1];
                bh[2*p+1][0] = b4[2]; bh[2*p+1][1] = b4[3];
            }
            #pragma unroll
            for (int mt = 0; mt < 4; mt++)
                #pragma unroll
                for (int nt = 0; nt < 4; nt++)
                    mma16816(acc[mt][nt], ah[mt], bh[nt]);
        }

        if (++st >= NSTAGE) st = 0;
    }

    // ---- epilogue ----
    #pragma unroll
    for (int mt = 0; mt < 4; mt++) {
        const int row0 = m_base + warp_m * 64 + mt * 16 + (lane >> 2);
        #pragma unroll
        for (int nt = 0; nt < 4; nt++) {
            const int col = warp_n * 32 + nt * 8 + (lane & 3) * 2;
            if (row0 < E_EDGES)
                *(float2*)&out[(size_t)row0 * 128 + col] =
                    make_float2(acc[mt][nt][0], acc[mt][nt][1]);
            if (row0 + 8 < E_EDGES)
                *(float2*)&out[(size_t)(row0 + 8) * 128 + col] =
                    make_float2(acc[mt][nt][2], acc[mt][nt][3]);
        }
    }
}

// ---------------------------------------------------------------------------
extern "C" void kernel_launch(void* const* d_in, const int* in_sizes, int n_in,
                              void* d_out, int out_size) {
    const float* rbf = (const float*)d_in[0];   // (E, 64, 16)
    const float* sph = (const float*)d_in[1];   // (E, 16, 16)
    const float* m   = (const float*)d_in[2];   // (E*8, 128)
    const float* w   = (const float*)d_in[3];   // (128, 64, 128)
    float* out = (float*)d_out;

    cudaFuncSetAttribute(gemm_kernel, cudaFuncAttributeMaxDynamicSharedMemorySize, SMEM_TOTAL_GEMM);

    wsplit_kernel<<<128, 256>>>(w);
    prep_kernel<<<EPAD / 2, 256>>>(rbf, sph, m);
    gemm_kernel<<<MTILES, 256, SMEM_TOTAL_GEMM>>>(out);
}